// round 1
// baseline (speedup 1.0000x reference)
#include <cuda_runtime.h>
#include <cuda_bf16.h>
#include <cstdint>

// Problem constants
#define RR 2048
#define CC 2048
#define DD 64
#define OO 4
#define NPAIR 10
#define KDIM (OO*DD + NPAIR + 1)   // 267
#define KP 272                     // padded K (17 * 16)

// GEMM tiling
#define BM 128
#define BN 128
#define BK 16
#define NTHREADS 256

// Packed f32x2 helpers (Blackwell: fma.rn.f32x2 is PTX-only)
#define FMA_F32X2(d, a, b, c) \
    asm("fma.rn.f32x2 %0, %1, %2, %3;" : "=l"(d) : "l"(a), "l"(b), "l"(c))
#define PACK_F32X2(out, lo, hi) \
    asm("mov.b64 %0, {%1, %2};" : "=l"(out) : "r"(lo), "r"(hi))
#define UNPACK_F32X2(lo, hi, in) \
    asm("mov.b64 {%0, %1}, %2;" : "=r"(lo), "=r"(hi) : "l"(in))

// Scratch (device globals: no allocation allowed)
__device__ float g_A[RR * KP];   // ~2.2 MB
__device__ float g_B[CC * KP];   // ~2.2 MB

// ---------------------------------------------------------------------------
// init: zero the scalar output (harness poisons it with 0xAA)
// ---------------------------------------------------------------------------
__global__ void init_out_kernel(float* out) {
    out[0] = 0.0f;
}

// ---------------------------------------------------------------------------
// prep_rows: one warp per row r.
//   A[r, o*64+d]   = z_rows[o,r,d]
//   A[r, 256+p]    = S[r,p] = dot(z_rows[o1,r,:], z_rows[o2,r,:]), pairs o1<=o2
//   A[r, 266]      = 1
//   A[r, 267..271] = 0
// ---------------------------------------------------------------------------
__global__ void prep_rows_kernel(const float* __restrict__ z_rows) {
    int gwarp = (blockIdx.x * blockDim.x + threadIdx.x) >> 5;
    int lane  = threadIdx.x & 31;
    if (gwarp >= RR) return;
    int r = gwarp;

    float z[OO][2];
#pragma unroll
    for (int o = 0; o < OO; o++) {
#pragma unroll
        for (int j = 0; j < 2; j++) {
            int d = lane + j * 32;
            float v = z_rows[(size_t)o * RR * DD + (size_t)r * DD + d];
            z[o][j] = v;
            g_A[(size_t)r * KP + o * DD + d] = v;
        }
    }

    int p = 0;
#pragma unroll
    for (int o1 = 0; o1 < OO; o1++) {
#pragma unroll
        for (int o2 = o1; o2 < OO; o2++) {
            float part = z[o1][0] * z[o2][0] + z[o1][1] * z[o2][1];
#pragma unroll
            for (int off = 16; off > 0; off >>= 1)
                part += __shfl_xor_sync(0xFFFFFFFFu, part, off);
            if (lane == 0)
                g_A[(size_t)r * KP + OO * DD + p] = part;
            p++;
        }
    }
    if (lane == 0)
        g_A[(size_t)r * KP + 266] = 1.0f;
    if (lane < KP - KDIM)
        g_A[(size_t)r * KP + KDIM + lane] = 0.0f;
}

// ---------------------------------------------------------------------------
// prep_cols: one warp per column c. coef[o] = t^o / o!
//   B[c, o*64+d]   = -2 * coef[o] * z_cols[c,d]
//   B[c, 256+p]    = (o1==o2 ? 1 : 2) * coef[o1]*coef[o2]
//   B[c, 266]      = ||z_cols[c]||^2
//   B[c, 267..271] = 0
// ---------------------------------------------------------------------------
__global__ void prep_cols_kernel(const float* __restrict__ z_cols,
                                 const float* __restrict__ col_times) {
    int gwarp = (blockIdx.x * blockDim.x + threadIdx.x) >> 5;
    int lane  = threadIdx.x & 31;
    if (gwarp >= CC) return;
    int c = gwarp;

    float t = col_times[c];
    float coef[OO];
    coef[0] = 1.0f;
    coef[1] = t;
    coef[2] = t * t * 0.5f;
    coef[3] = t * t * t * (1.0f / 6.0f);

    float zc[2];
    float zc2 = 0.0f;
#pragma unroll
    for (int j = 0; j < 2; j++) {
        int d = lane + j * 32;
        zc[j] = z_cols[(size_t)c * DD + d];
        zc2 += zc[j] * zc[j];
    }
#pragma unroll
    for (int off = 16; off > 0; off >>= 1)
        zc2 += __shfl_xor_sync(0xFFFFFFFFu, zc2, off);

#pragma unroll
    for (int o = 0; o < OO; o++) {
#pragma unroll
        for (int j = 0; j < 2; j++) {
            int d = lane + j * 32;
            g_B[(size_t)c * KP + o * DD + d] = -2.0f * coef[o] * zc[j];
        }
    }

    if (lane == 0) {
        int p = 0;
#pragma unroll
        for (int o1 = 0; o1 < OO; o1++) {
#pragma unroll
            for (int o2 = o1; o2 < OO; o2++) {
                float f = (o1 == o2) ? 1.0f : 2.0f;
                g_B[(size_t)c * KP + OO * DD + p] = f * coef[o1] * coef[o2];
                p++;
            }
        }
        g_B[(size_t)c * KP + 266] = zc2;
    }
    if (lane < KP - KDIM)
        g_B[(size_t)c * KP + KDIM + lane] = 0.0f;
}

// ---------------------------------------------------------------------------
// Fused GEMM + epilogue.
//   dist2[r,c] = sum_k A[r,k]*B[c,k]
//   logit = gr[r] + gc[c] - sqrt(dist2)
//   x = events ? logit : -logit ;  accumulate log_sigmoid(x); out += -sum
// 128x128 tile, 256 threads, 8x8 micro-tile, packed f32x2 FMAs.
// ---------------------------------------------------------------------------
__global__ __launch_bounds__(NTHREADS, 2)
void gemm_epilogue_kernel(const int* __restrict__ events,
                          const float* __restrict__ gamma_rows,
                          const float* __restrict__ gamma_cols,
                          float* __restrict__ out) {
    __shared__ float As[BK][BM];
    __shared__ float Bs[BK][BN];
    __shared__ float red[NTHREADS];

    const int tid = threadIdx.x;
    const int tx = tid & 15;         // 0..15 -> column group
    const int ty = tid >> 4;         // 0..15 -> row group
    const int row0 = blockIdx.y * BM;
    const int col0 = blockIdx.x * BN;

    // Per-tile load mapping: thread -> (row = tid/4 [+64], k4 = tid%4)
    const int lr  = tid >> 2;        // 0..63
    const int lk  = (tid & 3) * 4;   // 0,4,8,12

    unsigned long long acc[8][4];
#pragma unroll
    for (int i = 0; i < 8; i++)
#pragma unroll
        for (int j = 0; j < 4; j++)
            acc[i][j] = 0ULL;

    for (int kt = 0; kt < KP / BK; kt++) {
        const int kbase = kt * BK;
        // load A tile (transposed into smem)
#pragma unroll
        for (int half = 0; half < 2; half++) {
            int r = row0 + lr + half * 64;
            float4 v = *(const float4*)&g_A[(size_t)r * KP + kbase + lk];
            As[lk + 0][lr + half * 64] = v.x;
            As[lk + 1][lr + half * 64] = v.y;
            As[lk + 2][lr + half * 64] = v.z;
            As[lk + 3][lr + half * 64] = v.w;
        }
        // load B tile
#pragma unroll
        for (int half = 0; half < 2; half++) {
            int c = col0 + lr + half * 64;
            float4 v = *(const float4*)&g_B[(size_t)c * KP + kbase + lk];
            Bs[lk + 0][lr + half * 64] = v.x;
            Bs[lk + 1][lr + half * 64] = v.y;
            Bs[lk + 2][lr + half * 64] = v.z;
            Bs[lk + 3][lr + half * 64] = v.w;
        }
        __syncthreads();

#pragma unroll
        for (int k = 0; k < BK; k++) {
            float4 a0 = *(const float4*)&As[k][ty * 8];
            float4 a1 = *(const float4*)&As[k][ty * 8 + 4];
            const unsigned long long* bp =
                (const unsigned long long*)&Bs[k][tx * 8];
            unsigned long long bb0 = bp[0];
            unsigned long long bb1 = bp[1];
            unsigned long long bb2 = bp[2];
            unsigned long long bb3 = bp[3];

            float a[8] = {a0.x, a0.y, a0.z, a0.w, a1.x, a1.y, a1.z, a1.w};
#pragma unroll
            for (int i = 0; i < 8; i++) {
                unsigned long long aa;
                unsigned int ar = __float_as_uint(a[i]);
                PACK_F32X2(aa, ar, ar);
                FMA_F32X2(acc[i][0], aa, bb0, acc[i][0]);
                FMA_F32X2(acc[i][1], aa, bb1, acc[i][1]);
                FMA_F32X2(acc[i][2], aa, bb2, acc[i][2]);
                FMA_F32X2(acc[i][3], aa, bb3, acc[i][3]);
            }
        }
        __syncthreads();
    }

    // Epilogue: dist2 -> log-sigmoid contributions
    float grs[8], gcs[8];
#pragma unroll
    for (int i = 0; i < 8; i++) grs[i] = gamma_rows[row0 + ty * 8 + i];
#pragma unroll
    for (int j = 0; j < 8; j++) gcs[j] = gamma_cols[col0 + tx * 8 + j];

    const int* evbase = events + (size_t)(row0 + ty * 8) * CC + col0 + tx * 8;

    float lsum = 0.0f;
#pragma unroll
    for (int i = 0; i < 8; i++) {
        const int* evrow = evbase + (size_t)i * CC;
#pragma unroll
        for (int jp = 0; jp < 4; jp++) {
            unsigned int lo, hi;
            UNPACK_F32X2(lo, hi, acc[i][jp]);
            float d2[2] = {__uint_as_float(lo), __uint_as_float(hi)};
#pragma unroll
            for (int h = 0; h < 2; h++) {
                int j = jp * 2 + h;
                float dist = sqrtf(fmaxf(d2[h], 0.0f));
                float logit = grs[i] + gcs[j] - dist;
                int e = evrow[j];
                float x = (e == 1) ? logit : -logit;
                // log_sigmoid(x) = min(x,0) - log(1 + exp(-|x|))
                lsum += fminf(x, 0.0f) - __logf(1.0f + __expf(-fabsf(x)));
            }
        }
    }

    // block reduction
    red[tid] = lsum;
    __syncthreads();
#pragma unroll
    for (int s = NTHREADS / 2; s > 0; s >>= 1) {
        if (tid < s) red[tid] += red[tid + s];
        __syncthreads();
    }
    if (tid == 0)
        atomicAdd(out, -red[0]);
}

// ---------------------------------------------------------------------------
// launch
// ---------------------------------------------------------------------------
extern "C" void kernel_launch(void* const* d_in, const int* in_sizes, int n_in,
                              void* d_out, int out_size) {
    const int*   events     = (const int*)d_in[0];
    const float* col_times  = (const float*)d_in[1];
    const float* z_rows     = (const float*)d_in[2];
    const float* z_cols     = (const float*)d_in[3];
    const float* gamma_rows = (const float*)d_in[4];
    const float* gamma_cols = (const float*)d_in[5];
    float* out = (float*)d_out;

    init_out_kernel<<<1, 1>>>(out);

    // 8 warps / block, 1 warp per row/col
    prep_rows_kernel<<<RR / 8, 256>>>(z_rows);
    prep_cols_kernel<<<CC / 8, 256>>>(z_cols, col_times);

    dim3 grid(CC / BN, RR / BM);
    gemm_epilogue_kernel<<<grid, NTHREADS>>>(events, gamma_rows, gamma_cols, out);
}

// round 3
// speedup vs baseline: 2.9119x; 2.9119x over previous
#include <cuda_runtime.h>
#include <cstdint>

// Problem constants
#define RR 2048
#define CC 2048
#define DD 64
#define OO 4
#define KP 272            // 256 z-terms + 10 pair + 1 const + 5 zero ; 17 * 16
#define NCHUNK 17         // K chunks of 16

// GEMM tiling
#define BM 128
#define BN 256
#define BK 16
#define NTHREADS 256
#define NSTAGE 4
// per-stage smem: A 128x16 fp32 (8KB) + B 256x16 fp32 (16KB) = 24KB
#define STAGE_FLOATS 6144
#define SMEM_BYTES (NSTAGE * STAGE_FLOATS * 4)   // 98304

// ---------------------------------------------------------------------------
// Scratch in pre-swizzled tile-image layout (device globals; no allocation).
//   A: [mtile(16)][chunk(17)][128 rows][16 floats]  (2048 floats / chunk-tile)
//   B: [ntile(8) ][chunk(17)][256 rows][16 floats]  (4096 floats / chunk-tile)
// In-row layout: two k8 groups; within a group, k order [0,4,1,5,2,6,3,7]
// packed as 4 8-byte units; unit index XOR-swizzled with row bit1 (<<2).
// ---------------------------------------------------------------------------
__device__ float g_A[(size_t)16 * NCHUNK * 2048];
__device__ float g_B[(size_t)8  * NCHUNK * 4096];

__device__ __forceinline__ float tf32r(float x) {
    float y;
    asm("cvt.rna.tf32.f32 %0, %1;" : "=f"(y) : "f"(x));
    return y;
}

__device__ __forceinline__ size_t idxA(int r, int k) {
    int mt = r >> 7, m = r & 127;
    int ck = k >> 4, kk = k & 15;
    int k8 = kk >> 3, j = kk & 7;
    int u  = (k8 << 2) | (j & 3);
    int pu = u ^ (((m >> 1) & 1) << 2);
    int off = m * 16 + pu * 2 + (j >> 2);
    return ((size_t)(mt * NCHUNK + ck) << 11) + off;
}

__device__ __forceinline__ size_t idxB(int c, int k) {
    int nt = c >> 8, n = c & 255;
    int ck = k >> 4, kk = k & 15;
    int k8 = kk >> 3, j = kk & 7;
    int u  = (k8 << 2) | (j & 3);
    int pu = u ^ (((n >> 1) & 1) << 2);
    int off = n * 16 + pu * 2 + (j >> 2);
    return ((size_t)(nt * NCHUNK + ck) << 12) + off;
}

#define MMA_TF32(c, a, b) \
    asm volatile("mma.sync.aligned.m16n8k8.row.col.f32.tf32.tf32.f32 " \
        "{%0,%1,%2,%3}, {%4,%5,%6,%7}, {%8,%9}, {%0,%1,%2,%3};" \
        : "+f"((c)[0]), "+f"((c)[1]), "+f"((c)[2]), "+f"((c)[3]) \
        : "r"((a)[0]), "r"((a)[1]), "r"((a)[2]), "r"((a)[3]), \
          "r"((b)[0]), "r"((b)[1]))

#define CP_ASYNC16(dst_u32, src_ptr) \
    asm volatile("cp.async.cg.shared.global [%0], [%1], 16;" \
                 :: "r"(dst_u32), "l"(src_ptr))

// ---------------------------------------------------------------------------
__global__ void init_out_kernel(float* out) { out[0] = 0.0f; }

// ---------------------------------------------------------------------------
// prep_rows: one warp per row r.
// ---------------------------------------------------------------------------
__global__ void prep_rows_kernel(const float* __restrict__ z_rows) {
    int gw = (blockIdx.x * blockDim.x + threadIdx.x) >> 5;
    int lane = threadIdx.x & 31;
    if (gw >= RR) return;
    int r = gw;

    float z[OO][2];
#pragma unroll
    for (int o = 0; o < OO; o++) {
#pragma unroll
        for (int j = 0; j < 2; j++) {
            int d = lane + j * 32;
            float v = z_rows[((size_t)o * RR + r) * DD + d];
            z[o][j] = v;
            g_A[idxA(r, o * DD + d)] = tf32r(v);
        }
    }
    int p = 0;
#pragma unroll
    for (int o1 = 0; o1 < OO; o1++) {
#pragma unroll
        for (int o2 = o1; o2 < OO; o2++) {
            float part = z[o1][0] * z[o2][0] + z[o1][1] * z[o2][1];
#pragma unroll
            for (int off = 16; off > 0; off >>= 1)
                part += __shfl_xor_sync(0xFFFFFFFFu, part, off);
            if (lane == 0) g_A[idxA(r, 256 + p)] = tf32r(part);
            p++;
        }
    }
    if (lane == 0) g_A[idxA(r, 266)] = 1.0f;
    if (lane < 5) g_A[idxA(r, 267 + lane)] = 0.0f;
}

// ---------------------------------------------------------------------------
// prep_cols: one warp per column c.
// ---------------------------------------------------------------------------
__global__ void prep_cols_kernel(const float* __restrict__ z_cols,
                                 const float* __restrict__ col_times) {
    int gw = (blockIdx.x * blockDim.x + threadIdx.x) >> 5;
    int lane = threadIdx.x & 31;
    if (gw >= CC) return;
    int c = gw;

    float t = col_times[c];
    float coef[OO];
    coef[0] = 1.0f;
    coef[1] = t;
    coef[2] = t * t * 0.5f;
    coef[3] = t * t * t * (1.0f / 6.0f);

    float zc[2];
    float zc2 = 0.0f;
#pragma unroll
    for (int j = 0; j < 2; j++) {
        int d = lane + j * 32;
        zc[j] = z_cols[(size_t)c * DD + d];
        zc2 += zc[j] * zc[j];
    }
#pragma unroll
    for (int off = 16; off > 0; off >>= 1)
        zc2 += __shfl_xor_sync(0xFFFFFFFFu, zc2, off);

#pragma unroll
    for (int o = 0; o < OO; o++) {
#pragma unroll
        for (int j = 0; j < 2; j++) {
            int d = lane + j * 32;
            g_B[idxB(c, o * DD + d)] = tf32r(-2.0f * coef[o] * zc[j]);
        }
    }
    if (lane == 0) {
        int p = 0;
#pragma unroll
        for (int o1 = 0; o1 < OO; o1++) {
#pragma unroll
            for (int o2 = o1; o2 < OO; o2++) {
                float f = (o1 == o2) ? 1.0f : 2.0f;
                g_B[idxB(c, 256 + p)] = tf32r(f * coef[o1] * coef[o2]);
                p++;
            }
        }
        g_B[idxB(c, 266)] = tf32r(zc2);
    }
    if (lane < 5) g_B[idxB(c, 267 + lane)] = 0.0f;
}

// ---------------------------------------------------------------------------
// tf32 mma.sync GEMM + fused epilogue.
// grid (8, 16): blockIdx.x -> n-tile (256 cols), blockIdx.y -> m-tile (128 rows)
// ---------------------------------------------------------------------------
__global__ void __launch_bounds__(NTHREADS, 1)
gemm_mma_kernel(const int* __restrict__ events,
                const float* __restrict__ gamma_rows,
                const float* __restrict__ gamma_cols,
                float* __restrict__ out) {
    extern __shared__ float smem[];
    const uint32_t smem_u = (uint32_t)__cvta_generic_to_shared(smem);

    const int tid  = threadIdx.x;
    const int wid  = tid >> 5;
    const int lane = tid & 31;
    const int wm   = wid >> 2;          // 0..1
    const int wn   = wid & 3;           // 0..3
    const int g    = lane >> 2;         // 0..7
    const int tg   = lane & 3;          // 0..3
    const int swzu = ((g >> 1) & 1) << 2;

    const float* Ag = g_A + ((size_t)(blockIdx.y * NCHUNK) << 11);
    const float* Bg = g_B + ((size_t)(blockIdx.x * NCHUNK) << 12);

    float acc[4][8][4];
#pragma unroll
    for (int mf = 0; mf < 4; mf++)
#pragma unroll
        for (int nf = 0; nf < 8; nf++)
#pragma unroll
            for (int q = 0; q < 4; q++)
                acc[mf][nf][q] = 0.0f;

    // ---- async-copy issue for chunk ck into stage st ----
    auto issue = [&](int ck, int st) {
        uint32_t sa = smem_u + (uint32_t)st * (STAGE_FLOATS * 4);
        const float* aSrc = Ag + ((size_t)ck << 11);
        const float* bSrc = Bg + ((size_t)ck << 12);
        // A: 512 16B lines, 2 per thread
#pragma unroll
        for (int i = 0; i < 2; i++) {
            int l = tid + i * 256;
            CP_ASYNC16(sa + l * 16, aSrc + l * 4);
        }
        // B: 1024 16B lines, 4 per thread
#pragma unroll
        for (int i = 0; i < 4; i++) {
            int l = tid + i * 256;
            CP_ASYNC16(sa + 8192 + l * 16, bSrc + l * 4);
        }
    };

    auto compute = [&](int st) {
        const float* As = smem + st * STAGE_FLOATS;
        const float* Bs = As + 2048;
#pragma unroll
        for (int s = 0; s < 2; s++) {
            const int pu = ((s << 2) | tg) ^ swzu;
            uint32_t a[4][4];
#pragma unroll
            for (int mf = 0; mf < 4; mf++) {
                const float* p = As + (wm * 64 + mf * 16 + g) * 16 + pu * 2;
                float2 lo = *(const float2*)p;
                float2 hi = *(const float2*)(p + 128);   // +8 rows
                a[mf][0] = __float_as_uint(lo.x);
                a[mf][1] = __float_as_uint(hi.x);
                a[mf][2] = __float_as_uint(lo.y);
                a[mf][3] = __float_as_uint(hi.y);
            }
            uint32_t b[8][2];
#pragma unroll
            for (int nf = 0; nf < 8; nf++) {
                const float* p = Bs + (wn * 64 + nf * 8 + g) * 16 + pu * 2;
                float2 v = *(const float2*)p;
                b[nf][0] = __float_as_uint(v.x);
                b[nf][1] = __float_as_uint(v.y);
            }
#pragma unroll
            for (int mf = 0; mf < 4; mf++)
#pragma unroll
                for (int nf = 0; nf < 8; nf++)
                    MMA_TF32(acc[mf][nf], a[mf], b[nf]);
        }
    };

    // ---- pipeline ----
#pragma unroll
    for (int s = 0; s < 3; s++) {
        issue(s, s);
        asm volatile("cp.async.commit_group;");
    }
    for (int ck = 0; ck < NCHUNK; ck++) {
        asm volatile("cp.async.wait_group 2;");
        __syncthreads();
        if (ck + 3 < NCHUNK) issue(ck + 3, (ck + 3) & 3);
        asm volatile("cp.async.commit_group;");   // empty groups keep count
        compute(ck & 3);
    }

    // ---- fused epilogue ----
    const int rbase = blockIdx.y * BM + wm * 64;
    const int cbase = blockIdx.x * BN + wn * 64;

    float lsum = 0.0f;
#pragma unroll
    for (int mf = 0; mf < 4; mf++) {
        const int r0 = rbase + mf * 16 + g;
        const float gr0 = gamma_rows[r0];
        const float gr1 = gamma_rows[r0 + 8];
#pragma unroll
        for (int nf = 0; nf < 8; nf++) {
            const int cc = cbase + nf * 8 + tg * 2;
            const float gc0 = gamma_cols[cc];
            const float gc1 = gamma_cols[cc + 1];
            int2 e0 = *(const int2*)(events + (size_t)r0 * CC + cc);
            int2 e1 = *(const int2*)(events + (size_t)(r0 + 8) * CC + cc);
            const float* d = acc[mf][nf];
            float gr[4] = {gr0, gr0, gr1, gr1};
            float gc[4] = {gc0, gc1, gc0, gc1};
            int   ev[4] = {e0.x, e0.y, e1.x, e1.y};
#pragma unroll
            for (int q = 0; q < 4; q++) {
                float dd = fmaxf(d[q], 0.0f);
                float dist = dd * rsqrtf(fmaxf(dd, 1e-20f));
                float logit = gr[q] + gc[q] - dist;
                float x = ev[q] ? logit : -logit;
                lsum += fminf(x, 0.0f) - __logf(1.0f + __expf(-fabsf(x)));
            }
        }
    }
#pragma unroll
    for (int off = 16; off > 0; off >>= 1)
        lsum += __shfl_xor_sync(0xFFFFFFFFu, lsum, off);
    if (lane == 0) atomicAdd(out, -lsum);
}

// ---------------------------------------------------------------------------
// launch
// ---------------------------------------------------------------------------
extern "C" void kernel_launch(void* const* d_in, const int* in_sizes, int n_in,
                              void* d_out, int out_size) {
    const int*   events     = (const int*)d_in[0];
    const float* col_times  = (const float*)d_in[1];
    const float* z_rows     = (const float*)d_in[2];
    const float* z_cols     = (const float*)d_in[3];
    const float* gamma_rows = (const float*)d_in[4];
    const float* gamma_cols = (const float*)d_in[5];
    float* out = (float*)d_out;

    static int configured = 0;
    if (!configured) {
        cudaFuncSetAttribute(gemm_mma_kernel,
                             cudaFuncAttributeMaxDynamicSharedMemorySize,
                             SMEM_BYTES);
        configured = 1;
    }

    init_out_kernel<<<1, 1>>>(out);
    prep_rows_kernel<<<RR / 8, 256>>>(z_rows);
    prep_cols_kernel<<<CC / 8, 256>>>(z_cols, col_times);

    dim3 grid(CC / BN, RR / BM);   // (8, 16)
    gemm_mma_kernel<<<grid, NTHREADS, SMEM_BYTES>>>(events, gamma_rows,
                                                    gamma_cols, out);
}